// round 5
// baseline (speedup 1.0000x reference)
#include <cuda_runtime.h>
#include <math.h>

#define HID   256
#define NHEAD 8
#define VDIM  32
#define BATCH 8
#define NI    4096
#define NL    1024
#define NO    4096
#define CAP   512
#define NBLK  4

__device__ float g_bufA[BATCH * NI * HID];
__device__ float g_bufB[BATCH * NI * HID];
__device__ float g_lh[BATCH * NL * HID];
__device__ float g_la[BATCH * NL * HID];
__device__ float g_lb[BATCH * NL * HID];
__device__ float g_lc[BATCH * NL * HID];
__device__ float g_ld[BATCH * NL * HID];
__device__ int   g_idx_d[NL * CAP];
__device__ float g_dst_d[NL * CAP];
__device__ int   g_cnt_d[NL];
__device__ int   g_idx_p[NL * CAP];
__device__ float g_dst_p[NL * CAP];
__device__ int   g_cnt_p[NL];
__device__ float g_ex[NHEAD * 64 * 32];
__device__ float g_ey[NHEAD * 64 * 32];
__device__ float g_rsx[NHEAD * 64];
__device__ float g_rsy[NHEAD * 64];

__device__ __forceinline__ float gelu_f(float x) {
    float t = tanhf(0.7978845608028654f * (x + 0.044715f * x * x * x));
    return 0.5f * x * (1.0f + t);
}

__device__ __forceinline__ float head_scale(const float* r, int h) {
    float arg = 0.78539808485763197f * (1.0f + sinf(r[h]));
    return (float)tan((double)arg);
}

// round fp32 -> tf32 (RNA), result kept in fp32 container
__device__ __forceinline__ float f2tf(float x) {
    unsigned u;
    asm("cvt.rna.tf32.f32 %0, %1;" : "=r"(u) : "f"(x));
    return __uint_as_float(u);
}

__device__ __forceinline__ void mma8f(float* c, const float* a, const float* b) {
    asm volatile(
        "mma.sync.aligned.m16n8k8.row.col.f32.tf32.tf32.f32 "
        "{%0,%1,%2,%3},{%4,%5,%6,%7},{%8,%9},{%0,%1,%2,%3};"
        : "+f"(c[0]), "+f"(c[1]), "+f"(c[2]), "+f"(c[3])
        : "r"(__float_as_uint(a[0])), "r"(__float_as_uint(a[1])),
          "r"(__float_as_uint(a[2])), "r"(__float_as_uint(a[3])),
          "r"(__float_as_uint(b[0])), "r"(__float_as_uint(b[1])));
}

// ---------------- encoder: gelu(x @ W[256,4]^T + b) -------------------------
__global__ void k_enc(const float* __restrict__ x, const float* __restrict__ w,
                      const float* __restrict__ b, float* __restrict__ out) {
    size_t idx = (size_t)blockIdx.x * 256 + threadIdx.x;
    size_t row = idx >> 8;
    int o = (int)(idx & 255);
    float acc = b[o];
#pragma unroll
    for (int i = 0; i < 4; i++) acc = fmaf(x[row * 4 + i], w[o * 4 + i], acc);
    out[idx] = gelu_f(acc);
}

// -------- percentile threshold + survivor lists via integer histogram -------
template <int NK, int QRES, int KRES, int QM, int MAXD2>
__global__ void k_thresh(float invden, int k0, float frac,
                         int* __restrict__ idxL, float* __restrict__ dstL,
                         int* __restrict__ cnt) {
    __shared__ int hist[MAXD2 + 1];
    __shared__ int pre[256];
    __shared__ int s_lo, s_hi;
    __shared__ float s_thr;
    int q = blockIdx.x, tid = threadIdx.x;
    int qa = (q % QRES) * QM, qb = (q / QRES) * QM;
    for (int i = tid; i <= MAXD2; i += 256) hist[i] = 0;
    __syncthreads();
    for (int k = tid; k < NK; k += 256) {
        int a = qa - (k % KRES), b = qb - (k / KRES);
        atomicAdd(&hist[a * a + b * b], 1);
    }
    __syncthreads();
    const int len = (MAXD2 + 256) / 256;
    int s0 = tid * len;
    int e0 = s0 + len; if (e0 > MAXD2 + 1) e0 = MAXD2 + 1;
    int loc = 0;
    for (int i = s0; i < e0; i++) loc += hist[i];
    pre[tid] = loc;
    __syncthreads();
    for (int ofs = 1; ofs < 256; ofs <<= 1) {
        int v = (tid >= ofs) ? pre[tid - ofs] : 0;
        __syncthreads();
        pre[tid] += v;
        __syncthreads();
    }
    int incl = pre[tid], excl = incl - loc;
    int t1 = k0 + 1, t2 = k0 + 2;
    if (excl < t1 && incl >= t1) {
        int c = excl;
        for (int i = s0; i < e0; i++) { c += hist[i]; if (c >= t1) { s_lo = i; break; } }
    }
    if (excl < t2 && incl >= t2) {
        int c = excl;
        for (int i = s0; i < e0; i++) { c += hist[i]; if (c >= t2) { s_hi = i; break; } }
    }
    __syncthreads();
    if (tid == 0) {
        float flo = (float)s_lo * invden, fhi = (float)s_hi * invden;
        s_thr = flo + frac * (fhi - flo);
    }
    __syncthreads();
    if (tid < 32) {
        int lane = tid, c = 0;
        float thr = s_thr;
        for (int base = 0; base < NK; base += 32) {
            int k = base + lane;
            int a = qa - (k % KRES), b = qb - (k / KRES);
            float m = (float)(a * a + b * b) * invden;
            bool p = (m <= thr);
            unsigned mb = __ballot_sync(0xffffffffu, p);
            if (p) {
                int pos = c + __popc(mb & ((1u << lane) - 1u));
                if (pos < CAP) { idxL[q * CAP + pos] = k; dstL[q * CAP + pos] = m; }
            }
            c += __popc(mb);
        }
        if (lane == 0) cnt[q] = (c < CAP) ? c : CAP;
    }
}

// ---------------- sparse masked attention (row max is exactly 0) ------------
__global__ __launch_bounds__(256) void k_att_sparse(
    const float* __restrict__ value, const float* __restrict__ r,
    const int* __restrict__ idxL, const float* __restrict__ dstL,
    const int* __restrict__ cnt, float* __restrict__ out, int NK_, int NQ_) {
    int q = blockIdx.x, h = blockIdx.y, tid = threadIdx.x;
    int n = cnt[q];
    float scale = head_scale(r, h);
    __shared__ float w_s[CAP];
    __shared__ int   i_s[CAP];
    __shared__ float red[256];
    float lsum = 0.0f;
    for (int j = tid; j < n; j += 256) {
        float e = expf(-__fmul_rn(dstL[q * CAP + j], scale));
        w_s[j] = e;
        i_s[j] = idxL[q * CAP + j];
        lsum += e;
    }
    red[tid] = lsum;
    __syncthreads();
    for (int s = 128; s > 0; s >>= 1) {
        if (tid < s) red[tid] += red[tid + s];
        __syncthreads();
    }
    float rden = 1.0f / red[0];
    int b = tid >> 5, v = tid & 31;
    const float* vb = value + (size_t)b * NK_ * HID + h * VDIM + v;
    float acc = 0.0f;
    for (int j = 0; j < n; j++) acc = fmaf(w_s[j], vb[(size_t)i_s[j] * HID], acc);
    out[((size_t)(b * NQ_ + q)) * HID + h * VDIM + v] = gelu_f(acc * rden);
}

// ---------------- up attention: separable exp tables -------------------------
__global__ void k_up_exp(const float* __restrict__ r, float* __restrict__ ex,
                         float* __restrict__ ey, float* __restrict__ rsx,
                         float* __restrict__ rsy) {
    int h = blockIdx.x, tid = threadIdx.x;
    float scale = head_scale(r, h);
    for (int e = tid; e < 2048; e += 256) {
        int i = e >> 5, j = e & 31;
        int d = i - 2 * j, mn = i & 1;
        float v = expf(__fmul_rn((float)(mn - d * d) * (1.0f / 8192.0f), scale));
        ex[h * 2048 + e] = v;
        ey[h * 2048 + e] = v;
    }
    __syncthreads();
    if (tid < 64) {
        float s = 0.0f;
        for (int j = 0; j < 32; j++) s += ex[h * 2048 + tid * 32 + j];
        rsx[h * 64 + tid] = s;
        rsy[h * 64 + tid] = s;
    }
}

// Stage 1: G1[h,qy,kx,(b,v)] = sum_ky ey[h][qy,ky] * value[b, ky*32+kx, h*32+v]
__global__ __launch_bounds__(256) void k_up_s1(const float* __restrict__ value,
                                               const float* __restrict__ ey,
                                               float* __restrict__ G1) {
    int kx = blockIdx.x, h = blockIdx.y, tid = threadIdx.x;
    __shared__ float eys[64][32];
    __shared__ float vs[32][256];
    for (int e = tid; e < 2048; e += 256) eys[e >> 5][e & 31] = ey[h * 2048 + e];
    int b = tid >> 5, v = tid & 31;
    const float* vp = value + ((size_t)b * NL + kx) * HID + h * VDIM + v;
#pragma unroll
    for (int ky = 0; ky < 32; ky++) vs[ky][tid] = vp[(size_t)ky * 32 * HID];
    __syncthreads();
    float* gp = G1 + ((size_t)h * 64 * 32 + kx) * 256 + tid;
#pragma unroll
    for (int qy = 0; qy < 64; qy += 4) {
        float a0 = 0.f, a1 = 0.f, a2 = 0.f, a3 = 0.f;
#pragma unroll
        for (int ky = 0; ky < 32; ky++) {
            float vv = vs[ky][tid];
            a0 = fmaf(eys[qy + 0][ky], vv, a0);
            a1 = fmaf(eys[qy + 1][ky], vv, a1);
            a2 = fmaf(eys[qy + 2][ky], vv, a2);
            a3 = fmaf(eys[qy + 3][ky], vv, a3);
        }
        gp[(size_t)(qy + 0) * 32 * 256] = a0;
        gp[(size_t)(qy + 1) * 32 * 256] = a1;
        gp[(size_t)(qy + 2) * 32 * 256] = a2;
        gp[(size_t)(qy + 3) * 32 * 256] = a3;
    }
}

// Stage 2: out = gelu( (sum_kx ex[qx,kx]*G1) / (sx*sy) )
__global__ __launch_bounds__(256) void k_up_s2(const float* __restrict__ G1,
                                               const float* __restrict__ ex,
                                               const float* __restrict__ rsx,
                                               const float* __restrict__ rsy,
                                               float* __restrict__ out) {
    int qy = blockIdx.x, h = blockIdx.y, tid = threadIdx.x;
    __shared__ float exs[64][32];
    __shared__ float gs[32][256];
    for (int e = tid; e < 2048; e += 256) exs[e >> 5][e & 31] = ex[h * 2048 + e];
    const float* gb = G1 + (size_t)(h * 64 + qy) * 32 * 256;
    for (int e = tid; e < 32 * 256; e += 256) gs[e >> 8][e & 255] = gb[e];
    __syncthreads();
    int b = tid >> 5, v = tid & 31;
    float sy = rsy[h * 64 + qy];
#pragma unroll
    for (int qx = 0; qx < 64; qx += 4) {
        float a0 = 0.f, a1 = 0.f, a2 = 0.f, a3 = 0.f;
#pragma unroll
        for (int kx = 0; kx < 32; kx++) {
            float g = gs[kx][tid];
            a0 = fmaf(exs[qx + 0][kx], g, a0);
            a1 = fmaf(exs[qx + 1][kx], g, a1);
            a2 = fmaf(exs[qx + 2][kx], g, a2);
            a3 = fmaf(exs[qx + 3][kx], g, a3);
        }
#pragma unroll
        for (int i = 0; i < 4; i++) {
            float acc = (i == 0) ? a0 : (i == 1) ? a1 : (i == 2) ? a2 : a3;
            float rdv = 1.0f / (rsx[h * 64 + qx + i] * sy);
            out[((size_t)b * NO + qy * 64 + qx + i) * HID + h * VDIM + v] = gelu_f(acc * rdv);
        }
    }
}

// ---------------- 3xTF32 tensor-core GEMM (2 CTAs/SM) -----------------------
// C[M,N] = act(A[M,K] @ W'[N,K]^T + bias + add). BM=128, BN=64, BK=32,
// 8 warps (4m x 2n), warp tile 32x32, mma.m16n8k8.tf32.
// Smem: hi/lo interleaved, XOR swizzle k ^ ((row&7)<<2), no padding.
#define ASTG (128 * 64)   /* floats per A stage: 128 rows x 32 k x {hi,lo} */
#define BSTG (64 * 64)
#define GSMEM ((2 * ASTG + 2 * BSTG) * 4)

__device__ __forceinline__ void st_hl(float* base, int row, int c4, float4 v) {
    int sw = (row & 7) << 2;
    float f0 = v.x, f1 = v.y, f2 = v.z, f3 = v.w;
    float h0 = f2tf(f0), h1 = f2tf(f1), h2 = f2tf(f2), h3 = f2tf(f3);
    *(float2*)&base[row * 64 + ((c4 + 0) ^ sw) * 2] = make_float2(h0, f2tf(f0 - h0));
    *(float2*)&base[row * 64 + ((c4 + 1) ^ sw) * 2] = make_float2(h1, f2tf(f1 - h1));
    *(float2*)&base[row * 64 + ((c4 + 2) ^ sw) * 2] = make_float2(h2, f2tf(f2 - h2));
    *(float2*)&base[row * 64 + ((c4 + 3) ^ sw) * 2] = make_float2(h3, f2tf(f3 - h3));
}

__global__ __launch_bounds__(256, 2) void k_gemm_mma(
    const float* __restrict__ A, const float* __restrict__ W,
    const float* __restrict__ bias, const float* __restrict__ add,
    float* __restrict__ C, int M, int N, int K, int dogelu, int wv) {
    extern __shared__ float sm[];
    float* As = sm;                 // [2][128][32][2]
    float* Bs = sm + 2 * ASTG;      // [2][64][32][2]

    int bm = blockIdx.x * 128, bn = blockIdx.y * 64;
    int tid = threadIdx.x, warp = tid >> 5, lane = tid & 31;
    int wm = warp & 3, wn = warp >> 2;
    int lr = lane >> 2, lc = lane & 3;

    float acc[2][4][4];
#pragma unroll
    for (int i = 0; i < 2; i++)
#pragma unroll
        for (int j = 0; j < 4; j++)
#pragma unroll
            for (int t = 0; t < 4; t++) acc[i][j][t] = 0.0f;

    // producer coords
    int rA[4], cA[4], rB[2], cB[2];
#pragma unroll
    for (int i = 0; i < 4; i++) {
        int f4 = i * 256 + tid;
        rA[i] = f4 >> 3; cA[i] = (f4 & 7) * 4;
    }
#pragma unroll
    for (int i = 0; i < 2; i++) {
        int f4 = i * 256 + tid;
        rB[i] = f4 >> 3; cB[i] = (f4 & 7) * 4;
    }

    float4 pa[4], pw[2];
#pragma unroll
    for (int i = 0; i < 4; i++)
        pa[i] = *(const float4*)(A + (size_t)(bm + rA[i]) * K + cA[i]);
#pragma unroll
    for (int i = 0; i < 2; i++) {
        if (wv) {
            int n = bn + rB[i];
            const float* wb = W + (n >> 5) * (HID * VDIM) + (n & 31);
            pw[i].x = wb[(cB[i] + 0) * 32]; pw[i].y = wb[(cB[i] + 1) * 32];
            pw[i].z = wb[(cB[i] + 2) * 32]; pw[i].w = wb[(cB[i] + 3) * 32];
        } else {
            pw[i] = *(const float4*)(W + (size_t)(bn + rB[i]) * K + cB[i]);
        }
    }
#pragma unroll
    for (int i = 0; i < 4; i++) st_hl(As, rA[i], cA[i], pa[i]);
#pragma unroll
    for (int i = 0; i < 2; i++) st_hl(Bs, rB[i], cB[i], pw[i]);
    __syncthreads();

    int NT = K / 32;
    int swl = lr << 2;
    for (int kt = 0; kt < NT; kt++) {
        int p = kt & 1;
        if (kt + 1 < NT) {
            int kof = (kt + 1) * 32;
#pragma unroll
            for (int i = 0; i < 4; i++)
                pa[i] = *(const float4*)(A + (size_t)(bm + rA[i]) * K + kof + cA[i]);
#pragma unroll
            for (int i = 0; i < 2; i++) {
                if (wv) {
                    int n = bn + rB[i];
                    const float* wb = W + (n >> 5) * (HID * VDIM) + (n & 31);
                    pw[i].x = wb[(kof + cB[i] + 0) * 32]; pw[i].y = wb[(kof + cB[i] + 1) * 32];
                    pw[i].z = wb[(kof + cB[i] + 2) * 32]; pw[i].w = wb[(kof + cB[i] + 3) * 32];
                } else {
                    pw[i] = *(const float4*)(W + (size_t)(bn + rB[i]) * K + kof + cB[i]);
                }
            }
        }
        const float* Ap = As + p * ASTG;
        const float* Bp = Bs + p * BSTG;
#pragma unroll
        for (int kk = 0; kk < 4; kk++) {
            int ks0 = ((kk * 8 + lc) ^ swl) * 2;
            int ks1 = ((kk * 8 + lc + 4) ^ swl) * 2;
            float ah[2][4], al[2][4], bh[4][2], bl[4][2];
#pragma unroll
            for (int mt = 0; mt < 2; mt++) {
                int rb = (wm * 32 + mt * 16 + lr) * 64;
                float2 q0 = *(const float2*)&Ap[rb + ks0];
                float2 q1 = *(const float2*)&Ap[rb + 512 + ks0];
                float2 q2 = *(const float2*)&Ap[rb + ks1];
                float2 q3 = *(const float2*)&Ap[rb + 512 + ks1];
                ah[mt][0] = q0.x; al[mt][0] = q0.y;
                ah[mt][1] = q1.x; al[mt][1] = q1.y;
                ah[mt][2] = q2.x; al[mt][2] = q2.y;
                ah[mt][3] = q3.x; al[mt][3] = q3.y;
            }
#pragma unroll
            for (int nt = 0; nt < 4; nt++) {
                int nb = (wn * 32 + nt * 8 + lr) * 64;
                float2 q0 = *(const float2*)&Bp[nb + ks0];
                float2 q1 = *(const float2*)&Bp[nb + ks1];
                bh[nt][0] = q0.x; bl[nt][0] = q0.y;
                bh[nt][1] = q1.x; bl[nt][1] = q1.y;
            }
#pragma unroll
            for (int mt = 0; mt < 2; mt++)
#pragma unroll
                for (int nt = 0; nt < 4; nt++) {
                    mma8f(acc[mt][nt], al[mt], bh[nt]);
                    mma8f(acc[mt][nt], ah[mt], bl[nt]);
                    mma8f(acc[mt][nt], ah[mt], bh[nt]);
                }
        }
        if (kt + 1 < NT) {
            float* Aq = As + (p ^ 1) * ASTG;
            float* Bq = Bs + (p ^ 1) * BSTG;
#pragma unroll
            for (int i = 0; i < 4; i++) st_hl(Aq, rA[i], cA[i], pa[i]);
#pragma unroll
            for (int i = 0; i < 2; i++) st_hl(Bq, rB[i], cB[i], pw[i]);
        }
        __syncthreads();
    }

    // epilogue
#pragma unroll
    for (int mt = 0; mt < 2; mt++) {
        int r0 = bm + wm * 32 + mt * 16 + lr;
        int r1 = r0 + 8;
#pragma unroll
        for (int nt = 0; nt < 4; nt++) {
            int col = bn + wn * 32 + nt * 8 + 2 * lc;
            float2 b2 = make_float2(0.f, 0.f);
            if (bias) b2 = *(const float2*)(bias + col);
            float2 v0, v1;
            v0.x = acc[mt][nt][0] + b2.x; v0.y = acc[mt][nt][1] + b2.y;
            v1.x = acc[mt][nt][2] + b2.x; v1.y = acc[mt][nt][3] + b2.y;
            if (add) {
                float2 a0 = *(const float2*)(add + (size_t)r0 * N + col);
                float2 a1 = *(const float2*)(add + (size_t)r1 * N + col);
                v0.x += a0.x; v0.y += a0.y; v1.x += a1.x; v1.y += a1.y;
            }
            if (dogelu) {
                v0.x = gelu_f(v0.x); v0.y = gelu_f(v0.y);
                v1.x = gelu_f(v1.x); v1.y = gelu_f(v1.y);
            }
            *(float2*)(C + (size_t)r0 * N + col) = v0;
            *(float2*)(C + (size_t)r1 * N + col) = v1;
        }
    }
}

// final linear HID->1: one warp per row
__global__ void k_fc2(const float* __restrict__ h, const float* __restrict__ w,
                      const float* __restrict__ b, float* __restrict__ out) {
    int row = blockIdx.x * 8 + (threadIdx.x >> 5);
    int lane = threadIdx.x & 31;
    const float* hr = h + (size_t)row * HID;
    float acc = 0.0f;
#pragma unroll
    for (int o = lane; o < HID; o += 32) acc = fmaf(hr[o], w[o], acc);
#pragma unroll
    for (int s = 16; s > 0; s >>= 1) acc += __shfl_xor_sync(0xffffffffu, acc, s);
    if (lane == 0) out[row] = acc + b[0];
}

static inline void gemm(const float* A, const float* W, const float* bias,
                        const float* add, float* C, int M, int N, int K,
                        int g, int wv) {
    dim3 gr(M / 128, N / 64);
    k_gemm_mma<<<gr, 256, GSMEM>>>(A, W, bias, add, C, M, N, K, g, wv);
}

extern "C" void kernel_launch(void* const* d_in, const int* in_sizes, int n_in,
                              void* d_out, int out_size) {
    const float* x      = (const float*)d_in[0];
    const float* enw    = (const float*)d_in[1];
    const float* enb    = (const float*)d_in[2];
    const float* down_r = (const float*)d_in[3];
    const float* down_w = (const float*)d_in[4];
    const float* pa_r   = (const float*)d_in[5];
    const float* pa_w   = (const float*)d_in[6];
    const float* mlp1_w = (const float*)d_in[7];
    const float* mlp1_b = (const float*)d_in[8];
    const float* mlp2_w = (const float*)d_in[9];
    const float* mlp2_b = (const float*)d_in[10];
    const float* res_w  = (const float*)d_in[11];
    const float* res_b  = (const float*)d_in[12];
    const float* up_r   = (const float*)d_in[13];
    const float* up_w   = (const float*)d_in[14];
    const float* de1w   = (const float*)d_in[15];
    const float* de1b   = (const float*)d_in[16];
    const float* de2w   = (const float*)d_in[17];
    const float* de2b   = (const float*)d_in[18];
    float* out = (float*)d_out;

    static int smem_set = 0;
    if (!smem_set) {
        cudaFuncSetAttribute(k_gemm_mma, cudaFuncAttributeMaxDynamicSharedMemorySize, GSMEM);
        smem_set = 1;
    }

    float *bufA, *bufB, *lh, *la, *lb, *lc, *ld, *ex, *ey, *rsx, *rsy, *dst_d, *dst_p;
    int *idx_d, *cnt_d, *idx_p, *cnt_p;
    cudaGetSymbolAddress((void**)&bufA, g_bufA);
    cudaGetSymbolAddress((void**)&bufB, g_bufB);
    cudaGetSymbolAddress((void**)&lh, g_lh);
    cudaGetSymbolAddress((void**)&la, g_la);
    cudaGetSymbolAddress((void**)&lb, g_lb);
    cudaGetSymbolAddress((void**)&lc, g_lc);
    cudaGetSymbolAddress((void**)&ld, g_ld);
    cudaGetSymbolAddress((void**)&ex, g_ex);
    cudaGetSymbolAddress((void**)&ey, g_ey);
    cudaGetSymbolAddress((void**)&rsx, g_rsx);
    cudaGetSymbolAddress((void**)&rsy, g_rsy);
    cudaGetSymbolAddress((void**)&dst_d, g_dst_d);
    cudaGetSymbolAddress((void**)&dst_p, g_dst_p);
    cudaGetSymbolAddress((void**)&idx_d, g_idx_d);
    cudaGetSymbolAddress((void**)&cnt_d, g_cnt_d);
    cudaGetSymbolAddress((void**)&idx_p, g_idx_p);
    cudaGetSymbolAddress((void**)&cnt_p, g_cnt_p);

    // encoder
    k_enc<<<BATCH * NI, 256>>>(x, enw, enb, bufA);

    // masks
    {
        double id = 0.02 * (double)(NI - 1);
        int k0 = (int)id;
        k_thresh<NI, 32, 64, 2, 7938><<<NL, 256>>>(1.0f / 8192.0f, k0,
                                                   (float)(id - k0), idx_d, dst_d, cnt_d);
        double ip = 0.10 * (double)(NL - 1);
        int k0p = (int)ip;
        k_thresh<NL, 32, 32, 1, 1922><<<NL, 256>>>(1.0f / 2048.0f, k0p,
                                                   (float)(ip - k0p), idx_p, dst_p, cnt_p);
    }

    // down attention 64^2 -> 32^2  (this GEMM is the profiled launch slot)
    gemm(bufA, down_w, 0, 0, bufB, BATCH * NI, HID, HID, 0, 1);
    k_att_sparse<<<dim3(NL, NHEAD), 256>>>(bufB, down_r, idx_d, dst_d, cnt_d, lh, NI, NL);

    // processor blocks
    for (int i = 0; i < NBLK; i++) {
        gemm(lh, pa_w + (size_t)i * NHEAD * HID * VDIM, 0, 0, la, BATCH * NL, HID, HID, 0, 1);
        k_att_sparse<<<dim3(NL, NHEAD), 256>>>(la, pa_r + i * NHEAD, idx_p, dst_p, cnt_p, lb, NL, NL);
        gemm(lb, mlp1_w + (size_t)i * HID * HID, mlp1_b + i * HID, 0, lc, BATCH * NL, HID, HID, 1, 0);
        gemm(lh, res_w + (size_t)i * HID * HID, res_b + i * HID, 0, ld, BATCH * NL, HID, HID, 0, 0);
        gemm(lc, mlp2_w + (size_t)i * HID * HID, mlp2_b + i * HID, ld, lh, BATCH * NL, HID, HID, 1, 0);
    }

    // up attention 32^2 -> 64^2 (separable)
    gemm(lh, up_w, 0, 0, la, BATCH * NL, HID, HID, 0, 1);
    k_up_exp<<<NHEAD, 256>>>(up_r, ex, ey, rsx, rsy);
    k_up_s1<<<dim3(32, NHEAD), 256>>>(la, ey, bufB);
    k_up_s2<<<dim3(64, NHEAD), 256>>>(bufB, ex, rsx, rsy, bufA);

    // decoder
    gemm(bufA, de1w, de1b, 0, bufB, BATCH * NI, HID, HID, 1, 0);
    k_fc2<<<BATCH * NI / 8, 256>>>(bufB, de2w, de2b, out);
}

// round 6
// speedup vs baseline: 1.1950x; 1.1950x over previous
#include <cuda_runtime.h>
#include <math.h>

#define HID   256
#define NHEAD 8
#define VDIM  32
#define BATCH 8
#define NI    4096
#define NL    1024
#define NO    4096
#define CAP   512
#define NBLK  4

__device__ float g_bufA[BATCH * NI * HID];
__device__ float g_bufB[BATCH * NI * HID];
__device__ float g_lh[BATCH * NL * HID];
__device__ float g_la[BATCH * NL * HID];
__device__ float g_lb[BATCH * NL * HID];
__device__ float g_lc[BATCH * NL * HID];
__device__ float g_ld[BATCH * NL * HID];
__device__ int   g_idx_d[NL * CAP];
__device__ float g_dst_d[NL * CAP];
__device__ int   g_cnt_d[NL];
__device__ int   g_idx_p[NL * CAP];
__device__ float g_dst_p[NL * CAP];
__device__ int   g_cnt_p[NL];
__device__ float g_ex[NHEAD * 64 * 32];
__device__ float g_ey[NHEAD * 64 * 32];
__device__ float g_rsx[NHEAD * 64];
__device__ float g_rsy[NHEAD * 64];

__device__ __forceinline__ float gelu_f(float x) {
    float t = tanhf(0.7978845608028654f * (x + 0.044715f * x * x * x));
    return 0.5f * x * (1.0f + t);
}

__device__ __forceinline__ float head_scale(const float* r, int h) {
    float arg = 0.78539808485763197f * (1.0f + sinf(r[h]));
    return (float)tan((double)arg);
}

__device__ __forceinline__ float f2tf(float x) {
    unsigned u;
    asm("cvt.rna.tf32.f32 %0, %1;" : "=r"(u) : "f"(x));
    return __uint_as_float(u);
}

__device__ __forceinline__ void mma8(float* c, const unsigned* a, const unsigned* b) {
    asm volatile(
        "mma.sync.aligned.m16n8k8.row.col.f32.tf32.tf32.f32 "
        "{%0,%1,%2,%3},{%4,%5,%6,%7},{%8,%9},{%0,%1,%2,%3};"
        : "+f"(c[0]), "+f"(c[1]), "+f"(c[2]), "+f"(c[3])
        : "r"(a[0]), "r"(a[1]), "r"(a[2]), "r"(a[3]), "r"(b[0]), "r"(b[1]));
}

// ---------------- encoder -----------------------------------------------
__global__ void k_enc(const float* __restrict__ x, const float* __restrict__ w,
                      const float* __restrict__ b, float* __restrict__ out) {
    size_t idx = (size_t)blockIdx.x * 256 + threadIdx.x;
    size_t row = idx >> 8;
    int o = (int)(idx & 255);
    float acc = b[o];
#pragma unroll
    for (int i = 0; i < 4; i++) acc = fmaf(x[row * 4 + i], w[o * 4 + i], acc);
    out[idx] = gelu_f(acc);
}

// -------- percentile threshold + survivor lists ---------------------------
template <int NK, int QRES, int KRES, int QM, int MAXD2>
__global__ void k_thresh(float invden, int k0, float frac,
                         int* __restrict__ idxL, float* __restrict__ dstL,
                         int* __restrict__ cnt) {
    __shared__ int hist[MAXD2 + 1];
    __shared__ int pre[256];
    __shared__ int s_lo, s_hi;
    __shared__ float s_thr;
    int q = blockIdx.x, tid = threadIdx.x;
    int qa = (q % QRES) * QM, qb = (q / QRES) * QM;
    for (int i = tid; i <= MAXD2; i += 256) hist[i] = 0;
    __syncthreads();
    for (int k = tid; k < NK; k += 256) {
        int a = qa - (k % KRES), b = qb - (k / KRES);
        atomicAdd(&hist[a * a + b * b], 1);
    }
    __syncthreads();
    const int len = (MAXD2 + 256) / 256;
    int s0 = tid * len;
    int e0 = s0 + len; if (e0 > MAXD2 + 1) e0 = MAXD2 + 1;
    int loc = 0;
    for (int i = s0; i < e0; i++) loc += hist[i];
    pre[tid] = loc;
    __syncthreads();
    for (int ofs = 1; ofs < 256; ofs <<= 1) {
        int v = (tid >= ofs) ? pre[tid - ofs] : 0;
        __syncthreads();
        pre[tid] += v;
        __syncthreads();
    }
    int incl = pre[tid], excl = incl - loc;
    int t1 = k0 + 1, t2 = k0 + 2;
    if (excl < t1 && incl >= t1) {
        int c = excl;
        for (int i = s0; i < e0; i++) { c += hist[i]; if (c >= t1) { s_lo = i; break; } }
    }
    if (excl < t2 && incl >= t2) {
        int c = excl;
        for (int i = s0; i < e0; i++) { c += hist[i]; if (c >= t2) { s_hi = i; break; } }
    }
    __syncthreads();
    if (tid == 0) {
        float flo = (float)s_lo * invden, fhi = (float)s_hi * invden;
        s_thr = flo + frac * (fhi - flo);
    }
    __syncthreads();
    if (tid < 32) {
        int lane = tid, c = 0;
        float thr = s_thr;
        for (int base = 0; base < NK; base += 32) {
            int k = base + lane;
            int a = qa - (k % KRES), b = qb - (k / KRES);
            float m = (float)(a * a + b * b) * invden;
            bool p = (m <= thr);
            unsigned mb = __ballot_sync(0xffffffffu, p);
            if (p) {
                int pos = c + __popc(mb & ((1u << lane) - 1u));
                if (pos < CAP) { idxL[q * CAP + pos] = k; dstL[q * CAP + pos] = m; }
            }
            c += __popc(mb);
        }
        if (lane == 0) cnt[q] = (c < CAP) ? c : CAP;
    }
}

// ---------------- sparse masked attention ---------------------------------
__global__ __launch_bounds__(256) void k_att_sparse(
    const float* __restrict__ value, const float* __restrict__ r,
    const int* __restrict__ idxL, const float* __restrict__ dstL,
    const int* __restrict__ cnt, float* __restrict__ out, int NK_, int NQ_) {
    int q = blockIdx.x, h = blockIdx.y, tid = threadIdx.x;
    int n = cnt[q];
    float scale = head_scale(r, h);
    __shared__ float w_s[CAP];
    __shared__ int   i_s[CAP];
    __shared__ float red[256];
    float lsum = 0.0f;
    for (int j = tid; j < n; j += 256) {
        float e = expf(-__fmul_rn(dstL[q * CAP + j], scale));
        w_s[j] = e;
        i_s[j] = idxL[q * CAP + j];
        lsum += e;
    }
    red[tid] = lsum;
    __syncthreads();
    for (int s = 128; s > 0; s >>= 1) {
        if (tid < s) red[tid] += red[tid + s];
        __syncthreads();
    }
    float rden = 1.0f / red[0];
    int b = tid >> 5, v = tid & 31;
    const float* vb = value + (size_t)b * NK_ * HID + h * VDIM + v;
    float a0 = 0.f, a1 = 0.f, a2 = 0.f, a3 = 0.f;
    int j = 0;
    for (; j + 4 <= n; j += 4) {
        a0 = fmaf(w_s[j + 0], vb[(size_t)i_s[j + 0] * HID], a0);
        a1 = fmaf(w_s[j + 1], vb[(size_t)i_s[j + 1] * HID], a1);
        a2 = fmaf(w_s[j + 2], vb[(size_t)i_s[j + 2] * HID], a2);
        a3 = fmaf(w_s[j + 3], vb[(size_t)i_s[j + 3] * HID], a3);
    }
    for (; j < n; j++) a0 = fmaf(w_s[j], vb[(size_t)i_s[j] * HID], a0);
    float acc = (a0 + a1) + (a2 + a3);
    out[((size_t)(b * NQ_ + q)) * HID + h * VDIM + v] = gelu_f(acc * rden);
}

// ---------------- up attention tables --------------------------------------
__global__ void k_up_exp(const float* __restrict__ r, float* __restrict__ ex,
                         float* __restrict__ ey, float* __restrict__ rsx,
                         float* __restrict__ rsy) {
    int h = blockIdx.x, tid = threadIdx.x;
    float scale = head_scale(r, h);
    for (int e = tid; e < 2048; e += 256) {
        int i = e >> 5, j = e & 31;
        int d = i - 2 * j, mn = i & 1;
        float v = expf(__fmul_rn((float)(mn - d * d) * (1.0f / 8192.0f), scale));
        ex[h * 2048 + e] = v;
        ey[h * 2048 + e] = v;
    }
    __syncthreads();
    if (tid < 64) {
        float s = 0.0f;
        for (int j = 0; j < 32; j++) s += ex[h * 2048 + tid * 32 + j];
        rsx[h * 64 + tid] = s;
        rsy[h * 64 + tid] = s;
    }
}

// Stage 1: contract ky
__global__ __launch_bounds__(256) void k_up_s1(const float* __restrict__ value,
                                               const float* __restrict__ ey,
                                               float* __restrict__ G1) {
    int kx = blockIdx.x, h = blockIdx.y, tid = threadIdx.x;
    __shared__ float eys[64][32];
    __shared__ float vs[32][256];
    for (int e = tid; e < 2048; e += 256) eys[e >> 5][e & 31] = ey[h * 2048 + e];
    int b = tid >> 5, v = tid & 31;
    const float* vp = value + ((size_t)b * NL + kx) * HID + h * VDIM + v;
#pragma unroll
    for (int ky = 0; ky < 32; ky++) vs[ky][tid] = vp[(size_t)ky * 32 * HID];
    __syncthreads();
    float* gp = G1 + ((size_t)h * 64 * 32 + kx) * 256 + tid;
#pragma unroll
    for (int qy = 0; qy < 64; qy += 4) {
        float a0 = 0.f, a1 = 0.f, a2 = 0.f, a3 = 0.f;
#pragma unroll
        for (int ky = 0; ky < 32; ky++) {
            float vv = vs[ky][tid];
            a0 = fmaf(eys[qy + 0][ky], vv, a0);
            a1 = fmaf(eys[qy + 1][ky], vv, a1);
            a2 = fmaf(eys[qy + 2][ky], vv, a2);
            a3 = fmaf(eys[qy + 3][ky], vv, a3);
        }
        gp[(size_t)(qy + 0) * 32 * 256] = a0;
        gp[(size_t)(qy + 1) * 32 * 256] = a1;
        gp[(size_t)(qy + 2) * 32 * 256] = a2;
        gp[(size_t)(qy + 3) * 32 * 256] = a3;
    }
}

// Stage 2: contract kx
__global__ __launch_bounds__(256) void k_up_s2(const float* __restrict__ G1,
                                               const float* __restrict__ ex,
                                               const float* __restrict__ rsx,
                                               const float* __restrict__ rsy,
                                               float* __restrict__ out) {
    int qy = blockIdx.x, h = blockIdx.y, tid = threadIdx.x;
    __shared__ float exs[64][32];
    __shared__ float gs[32][256];
    for (int e = tid; e < 2048; e += 256) exs[e >> 5][e & 31] = ex[h * 2048 + e];
    const float* gb = G1 + (size_t)(h * 64 + qy) * 32 * 256;
    for (int e = tid; e < 32 * 256; e += 256) gs[e >> 8][e & 255] = gb[e];
    __syncthreads();
    int b = tid >> 5, v = tid & 31;
    float sy = rsy[h * 64 + qy];
#pragma unroll
    for (int qx = 0; qx < 64; qx += 4) {
        float a0 = 0.f, a1 = 0.f, a2 = 0.f, a3 = 0.f;
#pragma unroll
        for (int kx = 0; kx < 32; kx++) {
            float g = gs[kx][tid];
            a0 = fmaf(exs[qx + 0][kx], g, a0);
            a1 = fmaf(exs[qx + 1][kx], g, a1);
            a2 = fmaf(exs[qx + 2][kx], g, a2);
            a3 = fmaf(exs[qx + 3][kx], g, a3);
        }
#pragma unroll
        for (int i = 0; i < 4; i++) {
            float acc = (i == 0) ? a0 : (i == 1) ? a1 : (i == 2) ? a2 : a3;
            float rdv = 1.0f / (rsx[h * 64 + qx + i] * sy);
            out[((size_t)b * NO + qy * 64 + qx + i) * HID + h * VDIM + v] = gelu_f(acc * rdv);
        }
    }
}

// ---------------- 3xTF32 tensor-core GEMM (R4 layout) -----------------------
// C = act( A[M,K1] @ W[N,K1]^T + (A2[M,K2] @ W2[N,K2]^T) + bias + bias2 ).
// BM=128, BN=128, BK=32, 8 warps (2m x 4n), warp tile 64x32.
// wv!=0: W read as value weights packed [h][j][v] (pair-1 only).
#define GTS (128 * 36)
#define GSMEM (8 * GTS * 4)
__global__ __launch_bounds__(256, 1) void k_gemm_mma(
    const float* __restrict__ A, const float* __restrict__ W,
    const float* __restrict__ A2, const float* __restrict__ W2,
    const float* __restrict__ bias, const float* __restrict__ bias2,
    float* __restrict__ C, int M, int N, int K1, int K2, int dogelu, int wv) {
    extern __shared__ float smem[];
    float* Ah = smem;
    float* Al = smem + 2 * GTS;
    float* Wh = smem + 4 * GTS;
    float* Wl = smem + 6 * GTS;

    int bm = blockIdx.x * 128, bn = blockIdx.y * 128;
    int tid = threadIdx.x;
    int warp = tid >> 5, lane = tid & 31;
    int wm = warp & 1, wn = warp >> 1;
    int lr = lane >> 2, lc = lane & 3;

    float acc[4][4][4];
#pragma unroll
    for (int i = 0; i < 4; i++)
#pragma unroll
        for (int j = 0; j < 4; j++)
#pragma unroll
            for (int t = 0; t < 4; t++) acc[i][j][t] = 0.0f;

    int rowA[4], c4A[4];
#pragma unroll
    for (int i = 0; i < 4; i++) {
        int f4 = i * 256 + tid;
        rowA[i] = f4 >> 3;
        c4A[i] = (f4 & 7) * 4;
    }

    int NT1 = K1 / 32;
    int NT = NT1 + K2 / 32;

    float4 pa[4], pw[4];
    // prefetch tile 0 (always pair 1)
#pragma unroll
    for (int i = 0; i < 4; i++) {
        pa[i] = *(const float4*)(A + (size_t)(bm + rowA[i]) * K1 + c4A[i]);
        if (wv) {
            int n = bn + rowA[i];
            const float* wb = W + (n >> 5) * (HID * VDIM) + (n & 31);
            pw[i].x = wb[(c4A[i] + 0) * 32]; pw[i].y = wb[(c4A[i] + 1) * 32];
            pw[i].z = wb[(c4A[i] + 2) * 32]; pw[i].w = wb[(c4A[i] + 3) * 32];
        } else {
            pw[i] = *(const float4*)(W + (size_t)(bn + rowA[i]) * K1 + c4A[i]);
        }
    }
#pragma unroll
    for (int i = 0; i < 4; i++) {
        float4 hi, lo;
        hi.x = f2tf(pa[i].x); lo.x = f2tf(pa[i].x - hi.x);
        hi.y = f2tf(pa[i].y); lo.y = f2tf(pa[i].y - hi.y);
        hi.z = f2tf(pa[i].z); lo.z = f2tf(pa[i].z - hi.z);
        hi.w = f2tf(pa[i].w); lo.w = f2tf(pa[i].w - hi.w);
        *(float4*)&Ah[rowA[i] * 36 + c4A[i]] = hi;
        *(float4*)&Al[rowA[i] * 36 + c4A[i]] = lo;
        hi.x = f2tf(pw[i].x); lo.x = f2tf(pw[i].x - hi.x);
        hi.y = f2tf(pw[i].y); lo.y = f2tf(pw[i].y - hi.y);
        hi.z = f2tf(pw[i].z); lo.z = f2tf(pw[i].z - hi.z);
        hi.w = f2tf(pw[i].w); lo.w = f2tf(pw[i].w - hi.w);
        *(float4*)&Wh[rowA[i] * 36 + c4A[i]] = hi;
        *(float4*)&Wl[rowA[i] * 36 + c4A[i]] = lo;
    }
    __syncthreads();

    for (int kt = 0; kt < NT; kt++) {
        int p = kt & 1;
        if (kt + 1 < NT) {
            int nt_ = kt + 1;
#pragma unroll
            for (int i = 0; i < 4; i++) {
                if (nt_ < NT1) {
                    int kof = nt_ * 32;
                    pa[i] = *(const float4*)(A + (size_t)(bm + rowA[i]) * K1 + kof + c4A[i]);
                    if (wv) {
                        int n = bn + rowA[i];
                        const float* wb = W + (n >> 5) * (HID * VDIM) + (n & 31);
                        pw[i].x = wb[(kof + c4A[i] + 0) * 32]; pw[i].y = wb[(kof + c4A[i] + 1) * 32];
                        pw[i].z = wb[(kof + c4A[i] + 2) * 32]; pw[i].w = wb[(kof + c4A[i] + 3) * 32];
                    } else {
                        pw[i] = *(const float4*)(W + (size_t)(bn + rowA[i]) * K1 + kof + c4A[i]);
                    }
                } else {
                    int kof = (nt_ - NT1) * 32;
                    pa[i] = *(const float4*)(A2 + (size_t)(bm + rowA[i]) * K2 + kof + c4A[i]);
                    pw[i] = *(const float4*)(W2 + (size_t)(bn + rowA[i]) * K2 + kof + c4A[i]);
                }
            }
        }
        const float* Ahp = Ah + p * GTS;
        const float* Alp = Al + p * GTS;
        const float* Whp = Wh + p * GTS;
        const float* Wlp = Wl + p * GTS;
#pragma unroll
        for (int kk = 0; kk < 4; kk++) {
            int c0 = kk * 8 + lc;
            unsigned ah[4][4], al_[4][4], bh[4][2], bl[4][2];
#pragma unroll
            for (int mt = 0; mt < 4; mt++) {
                int rb = wm * 64 + mt * 16 + lr;
                ah[mt][0] = __float_as_uint(Ahp[rb * 36 + c0]);
                ah[mt][1] = __float_as_uint(Ahp[(rb + 8) * 36 + c0]);
                ah[mt][2] = __float_as_uint(Ahp[rb * 36 + c0 + 4]);
                ah[mt][3] = __float_as_uint(Ahp[(rb + 8) * 36 + c0 + 4]);
                al_[mt][0] = __float_as_uint(Alp[rb * 36 + c0]);
                al_[mt][1] = __float_as_uint(Alp[(rb + 8) * 36 + c0]);
                al_[mt][2] = __float_as_uint(Alp[rb * 36 + c0 + 4]);
                al_[mt][3] = __float_as_uint(Alp[(rb + 8) * 36 + c0 + 4]);
            }
#pragma unroll
            for (int nt = 0; nt < 4; nt++) {
                int n = wn * 32 + nt * 8 + lr;
                bh[nt][0] = __float_as_uint(Whp[n * 36 + c0]);
                bh[nt][1] = __float_as_uint(Whp[n * 36 + c0 + 4]);
                bl[nt][0] = __float_as_uint(Wlp[n * 36 + c0]);
                bl[nt][1] = __float_as_uint(Wlp[n * 36 + c0 + 4]);
            }
#pragma unroll
            for (int mt = 0; mt < 4; mt++)
#pragma unroll
                for (int nt = 0; nt < 4; nt++) {
                    mma8(acc[mt][nt], al_[mt], bh[nt]);
                    mma8(acc[mt][nt], ah[mt], bl[nt]);
                    mma8(acc[mt][nt], ah[mt], bh[nt]);
                }
        }
        if (kt + 1 < NT) {
            float* Ahq = Ah + (p ^ 1) * GTS;
            float* Alq = Al + (p ^ 1) * GTS;
            float* Whq = Wh + (p ^ 1) * GTS;
            float* Wlq = Wl + (p ^ 1) * GTS;
#pragma unroll
            for (int i = 0; i < 4; i++) {
                float4 hi, lo;
                hi.x = f2tf(pa[i].x); lo.x = f2tf(pa[i].x - hi.x);
                hi.y = f2tf(pa[i].y); lo.y = f2tf(pa[i].y - hi.y);
                hi.z = f2tf(pa[i].z); lo.z = f2tf(pa[i].z - hi.z);
                hi.w = f2tf(pa[i].w); lo.w = f2tf(pa[i].w - hi.w);
                *(float4*)&Ahq[rowA[i] * 36 + c4A[i]] = hi;
                *(float4*)&Alq[rowA[i] * 36 + c4A[i]] = lo;
                hi.x = f2tf(pw[i].x); lo.x = f2tf(pw[i].x - hi.x);
                hi.y = f2tf(pw[i].y); lo.y = f2tf(pw[i].y - hi.y);
                hi.z = f2tf(pw[i].z); lo.z = f2tf(pw[i].z - hi.z);
                hi.w = f2tf(pw[i].w); lo.w = f2tf(pw[i].w - hi.w);
                *(float4*)&Whq[rowA[i] * 36 + c4A[i]] = hi;
                *(float4*)&Wlq[rowA[i] * 36 + c4A[i]] = lo;
            }
        }
        __syncthreads();
    }

    // epilogue
#pragma unroll
    for (int mt = 0; mt < 4; mt++) {
        int r0 = bm + wm * 64 + mt * 16 + lr;
        int r1 = r0 + 8;
#pragma unroll
        for (int nt = 0; nt < 4; nt++) {
            int col = bn + wn * 32 + nt * 8 + 2 * lc;
            float2 b2 = make_float2(0.f, 0.f);
            if (bias) b2 = *(const float2*)(bias + col);
            if (bias2) {
                float2 e2 = *(const float2*)(bias2 + col);
                b2.x += e2.x; b2.y += e2.y;
            }
            float2 v0, v1;
            v0.x = acc[mt][nt][0] + b2.x; v0.y = acc[mt][nt][1] + b2.y;
            v1.x = acc[mt][nt][2] + b2.x; v1.y = acc[mt][nt][3] + b2.y;
            if (dogelu) {
                v0.x = gelu_f(v0.x); v0.y = gelu_f(v0.y);
                v1.x = gelu_f(v1.x); v1.y = gelu_f(v1.y);
            }
            *(float2*)(C + (size_t)r0 * N + col) = v0;
            *(float2*)(C + (size_t)r1 * N + col) = v1;
        }
    }
}

// final linear HID->1
__global__ void k_fc2(const float* __restrict__ h, const float* __restrict__ w,
                      const float* __restrict__ b, float* __restrict__ out) {
    int row = blockIdx.x * 8 + (threadIdx.x >> 5);
    int lane = threadIdx.x & 31;
    const float* hr = h + (size_t)row * HID;
    float acc = 0.0f;
#pragma unroll
    for (int o = lane; o < HID; o += 32) acc = fmaf(hr[o], w[o], acc);
#pragma unroll
    for (int s = 16; s > 0; s >>= 1) acc += __shfl_xor_sync(0xffffffffu, acc, s);
    if (lane == 0) out[row] = acc + b[0];
}

static inline void gemm(const float* A, const float* W, const float* bias,
                        float* C, int M, int N, int K, int g, int wv) {
    dim3 gr(M / 128, N / 128);
    k_gemm_mma<<<gr, 256, GSMEM>>>(A, W, 0, 0, bias, 0, C, M, N, K, 0, g, wv);
}

static inline void gemm2(const float* A, const float* W,
                         const float* A2, const float* W2,
                         const float* bias, const float* bias2,
                         float* C, int M, int N, int K1, int K2, int g) {
    dim3 gr(M / 128, N / 128);
    k_gemm_mma<<<gr, 256, GSMEM>>>(A, W, A2, W2, bias, bias2, C, M, N, K1, K2, g, 0);
}

extern "C" void kernel_launch(void* const* d_in, const int* in_sizes, int n_in,
                              void* d_out, int out_size) {
    const float* x      = (const float*)d_in[0];
    const float* enw    = (const float*)d_in[1];
    const float* enb    = (const float*)d_in[2];
    const float* down_r = (const float*)d_in[3];
    const float* down_w = (const float*)d_in[4];
    const float* pa_r   = (const float*)d_in[5];
    const float* pa_w   = (const float*)d_in[6];
    const float* mlp1_w = (const float*)d_in[7];
    const float* mlp1_b = (const float*)d_in[8];
    const float* mlp2_w = (const float*)d_in[9];
    const float* mlp2_b = (const float*)d_in[10];
    const float* res_w  = (const float*)d_in[11];
    const float* res_b  = (const float*)d_in[12];
    const float* up_r   = (const float*)d_in[13];
    const float* up_w   = (const float*)d_in[14];
    const float* de1w   = (const float*)d_in[15];
    const float* de1b   = (const float*)d_in[16];
    const float* de2w   = (const float*)d_in[17];
    const float* de2b   = (const float*)d_in[18];
    float* out = (float*)d_out;

    static int smem_set = 0;
    if (!smem_set) {
        cudaFuncSetAttribute(k_gemm_mma, cudaFuncAttributeMaxDynamicSharedMemorySize, GSMEM);
        smem_set = 1;
    }

    float *bufA, *bufB, *lh, *la, *lb, *lc, *ld, *ex, *ey, *rsx, *rsy, *dst_d, *dst_p;
    int *idx_d, *cnt_d, *idx_p, *cnt_p;
    cudaGetSymbolAddress((void**)&bufA, g_bufA);
    cudaGetSymbolAddress((void**)&bufB, g_bufB);
    cudaGetSymbolAddress((void**)&lh, g_lh);
    cudaGetSymbolAddress((void**)&la, g_la);
    cudaGetSymbolAddress((void**)&lb, g_lb);
    cudaGetSymbolAddress((void**)&lc, g_lc);
    cudaGetSymbolAddress((void**)&ld, g_ld);
    cudaGetSymbolAddress((void**)&ex, g_ex);
    cudaGetSymbolAddress((void**)&ey, g_ey);
    cudaGetSymbolAddress((void**)&rsx, g_rsx);
    cudaGetSymbolAddress((void**)&rsy, g_rsy);
    cudaGetSymbolAddress((void**)&dst_d, g_dst_d);
    cudaGetSymbolAddress((void**)&dst_p, g_dst_p);
    cudaGetSymbolAddress((void**)&idx_d, g_idx_d);
    cudaGetSymbolAddress((void**)&cnt_d, g_cnt_d);
    cudaGetSymbolAddress((void**)&idx_p, g_idx_p);
    cudaGetSymbolAddress((void**)&cnt_p, g_cnt_p);

    // encoder
    k_enc<<<BATCH * NI, 256>>>(x, enw, enb, bufA);

    // masks
    {
        double id = 0.02 * (double)(NI - 1);
        int k0 = (int)id;
        k_thresh<NI, 32, 64, 2, 7938><<<NL, 256>>>(1.0f / 8192.0f, k0,
                                                   (float)(id - k0), idx_d, dst_d, cnt_d);
        double ip = 0.10 * (double)(NL - 1);
        int k0p = (int)ip;
        k_thresh<NL, 32, 32, 1, 1922><<<NL, 256>>>(1.0f / 2048.0f, k0p,
                                                   (float)(ip - k0p), idx_p, dst_p, cnt_p);
    }

    // down attention 64^2 -> 32^2  (profiled slot: big value GEMM)
    gemm(bufA, down_w, 0, bufB, BATCH * NI, HID, HID, 0, 1);
    k_att_sparse<<<dim3(NL, NHEAD), 256>>>(bufB, down_r, idx_d, dst_d, cnt_d, lh, NI, NL);

    // processor blocks: h alternates lh <-> ld to avoid in-place hazard
    float* hcur = lh;
    float* hnxt = ld;
    for (int i = 0; i < NBLK; i++) {
        gemm(hcur, pa_w + (size_t)i * NHEAD * HID * VDIM, 0, la, BATCH * NL, HID, HID, 0, 1);
        k_att_sparse<<<dim3(NL, NHEAD), 256>>>(la, pa_r + i * NHEAD, idx_p, dst_p, cnt_p, lb, NL, NL);
        gemm(lb, mlp1_w + (size_t)i * HID * HID, mlp1_b + i * HID, lc, BATCH * NL, HID, HID, 1, 0);
        // fused: h' = gelu(lc @ mlp2^T + hcur @ res^T + mlp2_b + res_b)
        gemm2(lc, mlp2_w + (size_t)i * HID * HID, hcur, res_w + (size_t)i * HID * HID,
              mlp2_b + i * HID, res_b + i * HID, hnxt, BATCH * NL, HID, HID, HID, 1);
        float* t = hcur; hcur = hnxt; hnxt = t;
    }

    // up attention 32^2 -> 64^2 (separable)
    gemm(hcur, up_w, 0, la, BATCH * NL, HID, HID, 0, 1);
    k_up_exp<<<NHEAD, 256>>>(up_r, ex, ey, rsx, rsy);
    k_up_s1<<<dim3(32, NHEAD), 256>>>(la, ey, bufB);
    k_up_s2<<<dim3(64, NHEAD), 256>>>(bufB, ex, rsx, rsy, bufA);

    // decoder
    gemm(bufA, de1w, de1b, bufB, BATCH * NI, HID, HID, 1, 0);
    k_fc2<<<BATCH * NI / 8, 256>>>(bufB, de2w, de2b, out);
}